// round 16
// baseline (speedup 1.0000x reference)
#include <cuda_runtime.h>

// Problem constants (fixed by the reference):
//   N_NODES = 2048, N_ELEMS = 4096
//   Output: (N + 2E) x (2E + N) = 10240 x 10240 fp32
#define NN 2048
#define EE 4096
#define WW (2 * EE + NN)   // 10240
#define W4 (WW / 4)        // 2560

// Copy+transpose tiles: 64x64 over M; each writes the kcl copy AND -M^T.
// They come FIRST so their M reads overlap the fill write stream and the
// kernel tail is pure writes.
#define TP_TILE 64
#define TP_TILES_X (EE / TP_TILE)                     // 64 (e tiles)
#define TP_TILES_Y (NN / TP_TILE)                     // 32 (n tiles)
#define NUM_TP_ITEMS (TP_TILES_X * TP_TILES_Y)        // 2048
// Fill: one block per output row; 256 threads x 5 chunks of 32B = row.
#define NUM_FILL_BLOCKS WW                            // 10240
#define TOTAL_BLOCKS (NUM_TP_ITEMS + NUM_FILL_BLOCKS) // 12288

// 256-bit global store (sm_100 family: STG.E.256).
__device__ __forceinline__ void stg256(float* p, float4 a, float4 b)
{
    asm volatile(
        "st.global.v8.f32 [%0], {%1, %2, %3, %4, %5, %6, %7, %8};"
        :: "l"(p),
           "f"(a.x), "f"(a.y), "f"(a.z), "f"(a.w),
           "f"(b.x), "f"(b.y), "f"(b.z), "f"(b.w)
        : "memory");
}

__global__ void __launch_bounds__(256) fused_kernel(
    const float* __restrict__ M,
    const float* __restrict__ params,
    const int* __restrict__ kinds,
    float* __restrict__ out)
{
    const int bid = blockIdx.x;
    const int tid = threadIdx.x;

    if (bid < NUM_TP_ITEMS) {
        // ------------------------------------------------------------------
        // COPY+TRANSPOSE tile, 64x64, 128-bit accesses (measured fastest).
        //   copy : out[n][e]           = M[n][e]
        //   trans: out[NN + e][2E + n] = -M[n][e]
        // ------------------------------------------------------------------
        __shared__ float tile[TP_TILE][TP_TILE + 1];   // [n_local][e_local]

        const int t  = bid;
        const int et = t % TP_TILES_X;
        const int nt = t / TP_TILES_X;
        const int e0 = et * TP_TILE;
        const int n0 = nt * TP_TILE;

        // Batch all 4 loads first (independent -> 4 outstanding LDG.128).
        float4 m4[4];
        #pragma unroll
        for (int j = 0; j < 4; j++) {
            const int idx  = tid + 256 * j;
            const int lrow = idx >> 4;        // n_local 0..63
            const int lc4  = idx & 15;        // e_local/4 0..15
            m4[j] = reinterpret_cast<const float4*>(
                M + (long)(n0 + lrow) * EE + e0)[lc4];
        }

        // kcl copy stores — straight from registers, coalesced.
        #pragma unroll
        for (int j = 0; j < 4; j++) {
            const int idx  = tid + 256 * j;
            const int lrow = idx >> 4;
            const int lc4  = idx & 15;
            reinterpret_cast<float4*>(
                out)[(long)(n0 + lrow) * W4 + (e0 >> 2) + lc4] = m4[j];
        }

        // Stage for transpose.
        #pragma unroll
        for (int j = 0; j < 4; j++) {
            const int idx  = tid + 256 * j;
            const int lrow = idx >> 4;
            const int lc4  = idx & 15;
            tile[lrow][lc4 * 4 + 0] = m4[j].x;
            tile[lrow][lc4 * 4 + 1] = m4[j].y;
            tile[lrow][lc4 * 4 + 2] = m4[j].z;
            tile[lrow][lc4 * 4 + 3] = m4[j].w;
        }
        __syncthreads();

        // Transposed stores: 4 coalesced float4 per thread.
        #pragma unroll
        for (int j = 0; j < 4; j++) {
            const int idx  = tid + 256 * j;
            const int orow = idx >> 4;        // e_local 0..63
            const int oc4  = idx & 15;        // n_local/4 0..15
            const int nl   = oc4 * 4;
            float4 v;
            v.x = -tile[nl + 0][orow];
            v.y = -tile[nl + 1][orow];
            v.z = -tile[nl + 2][orow];
            v.w = -tile[nl + 3][orow];
            reinterpret_cast<float4*>(
                out + (long)(NN + e0 + orow) * WW + 2 * EE + n0)[oc4] = v;
        }
    } else {
        // ------------------------------------------------------------------
        // FILL path: block owns one output row. Thread t writes 32-byte
        // chunk c8 = t + 256*i via STG.256.
        //   kcl : chunks i = 2..4  (M block by tiles)
        //   kvl : chunks i = 0..3  (-M^T by tiles)
        //   elem: chunks i = 0..4
        // ------------------------------------------------------------------
        const int row = bid - NUM_TP_ITEMS;
        float* orow = out + (long)row * WW;
        const float4 z4 = make_float4(0.f, 0.f, 0.f, 0.f);

        if (row < NN) {
            // kcl: [ M | 0 ]
            #pragma unroll
            for (int i = 2; i < 5; i++) {
                stg256(orow + (tid + 256 * i) * 8, z4, z4);
            }
        } else if (row < NN + EE) {
            // kvl: [ 0 | I_E | (-M^T by tiles) ]
            const int r   = row - NN;
            const int d   = EE + r;          // identity column
            const int dc8 = d >> 3;
            const int dl  = d & 7;
            #pragma unroll
            for (int i = 0; i < 4; i++) {
                const int c8 = tid + 256 * i;
                float4 aa = z4, bb = z4;
                if (c8 == dc8) {
                    if (dl < 4) reinterpret_cast<float*>(&aa)[dl]     = 1.0f;
                    else        reinterpret_cast<float*>(&bb)[dl - 4] = 1.0f;
                }
                stg256(orow + c8 * 8, aa, bb);
            }
        } else {
            // elem: zeros + z diag at col=pos, y diag at col=E+pos.
            const int pos = row - NN - EE;
            const float p = params[pos];
            const int   k = kinds[pos];
            float zv = 0.0f;
            if (k == 0)                      zv = -p;   // R
            else if (k == 2)                 zv = 1.0f; // VC
            else if (k == 3 && !(p > 0.0f))  zv = 1.0f; // SW off
            const float yv = (k == 0 || k == 1 || (k == 3 && p > 0.0f)) ? 1.0f : 0.0f;

            const int zc8 = pos >> 3;
            const int yc8 = (EE + pos) >> 3;
            const int l   = pos & 7;         // same sub-lane (EE % 8 == 0)

            #pragma unroll
            for (int i = 0; i < 5; i++) {
                const int c8 = tid + 256 * i;
                float4 aa = z4, bb = z4;
                if (c8 == zc8) {
                    if (l < 4) reinterpret_cast<float*>(&aa)[l]     = zv;
                    else       reinterpret_cast<float*>(&bb)[l - 4] = zv;
                }
                if (c8 == yc8) {
                    if (l < 4) reinterpret_cast<float*>(&aa)[l]     = yv;
                    else       reinterpret_cast<float*>(&bb)[l - 4] = yv;
                }
                stg256(orow + c8 * 8, aa, bb);
            }
        }
    }
}

extern "C" void kernel_launch(void* const* d_in, const int* in_sizes, int n_in,
                              void* d_out, int out_size)
{
    const float* M      = (const float*)d_in[0];
    const float* params = (const float*)d_in[1];
    const int*   kinds  = (const int*)d_in[2];
    float*       out    = (float*)d_out;

    (void)in_sizes; (void)n_in; (void)out_size;

    fused_kernel<<<TOTAL_BLOCKS, 256>>>(M, params, kinds, out);
}